// round 2
// baseline (speedup 1.0000x reference)
#include <cuda_runtime.h>

#define HW    4096
#define NB    4
#define LOG2E 1.44269504088896340736f

// ---------------- scratch (device globals: allocation-free) ----------------
__device__ float g_Qc[NB * 64 * HW];   // [b][c][n], pre-scaled by log2e
__device__ float g_Kc[NB * 64 * HW];   // [b][c][n]
__device__ float g_Vw[NB * HW * 64];   // [b][n][c]  (w folded in)
__device__ float g_w [NB * HW];        // w[m] = 1 + beta*edge

// ---------------- f32x2 packed-FMA helpers (FFMA2) ----------------
__device__ __forceinline__ double dup2(float x) {
    double r; asm("mov.b64 %0, {%1,%1};" : "=d"(r) : "f"(x)); return r;
}
__device__ __forceinline__ void ffma2(double &d, double a, double b) {
    asm("fma.rn.f32x2 %0, %1, %2, %0;" : "+d"(d) : "d"(a), "d"(b));
}
__device__ __forceinline__ double fmul2(double a, double b) {
    double r; asm("mul.rn.f32x2 %0, %1, %2;" : "=d"(r) : "d"(a), "d"(b)); return r;
}
__device__ __forceinline__ void unpack2(double v, float &lo, float &hi) {
    asm("mov.b64 {%0,%1}, %2;" : "=f"(lo), "=f"(hi) : "d"(v));
}
__device__ __forceinline__ float ex2f(float x) {
    float r; asm("ex2.approx.f32 %0, %1;" : "=f"(r) : "f"(x)); return r;
}

// ================= kernel 1: edge detector -> g_w =================
// 3x3 conv (64->32) + folded BN + ReLU + 1x1 (32->1) + sigmoid
__global__ __launch_bounds__(128) void edge_kernel(
    const float* __restrict__ x,  const float* __restrict__ We1,
    const float* __restrict__ be1,
    const float* __restrict__ bn_w, const float* __restrict__ bn_b,
    const float* __restrict__ bn_mean, const float* __restrict__ bn_var,
    const float* __restrict__ We2, const float* __restrict__ be2,
    const float* __restrict__ beta)
{
    __shared__ __align__(16) float Wsh[32 * 9 * 32];   // [cc][k][ch] chunk
    __shared__ float s_sc[32], s_sh[32], s_w2[32];

    const int tid = threadIdx.x;
    const int b   = blockIdx.y;
    const int p   = blockIdx.x * 128 + tid;
    const int h   = p >> 6, w = p & 63;

    if (tid < 32) {
        float s = bn_w[tid] * rsqrtf(bn_var[tid] + 1e-5f);
        s_sc[tid] = s;
        s_sh[tid] = (be1[tid] - bn_mean[tid]) * s + bn_b[tid];
        s_w2[tid] = We2[tid];
    }

    double acc2[16];
    #pragma unroll
    for (int i = 0; i < 16; i++) acc2[i] = 0.0;

    for (int chunk = 0; chunk < 2; chunk++) {
        __syncthreads();
        for (int e = tid; e < 32 * 9 * 32; e += 128) {
            int ch = e & 31, rest = e >> 5;
            int k = rest % 9, cc = rest / 9;
            Wsh[e] = We1[((ch * 64) + (chunk * 32 + cc)) * 9 + k];
        }
        __syncthreads();
        const float* xb = x + (size_t)(b * 64 + chunk * 32) * HW;
        for (int cc = 0; cc < 32; cc++) {
            const float* xc = xb + cc * HW;
            #pragma unroll
            for (int k = 0; k < 9; k++) {
                const int dy = k / 3 - 1, dx = k % 3 - 1;
                const int hh = h + dy, ww = w + dx;
                float xv = 0.f;
                if (hh >= 0 && hh < 64 && ww >= 0 && ww < 64) xv = xc[hh * 64 + ww];
                double dv = dup2(xv);
                const double* wrow = (const double*)&Wsh[(cc * 9 + k) * 32];
                #pragma unroll
                for (int c2 = 0; c2 < 16; c2++) ffma2(acc2[c2], dv, wrow[c2]);
            }
        }
    }

    float e2 = be2[0];
    #pragma unroll
    for (int c2 = 0; c2 < 16; c2++) {
        float a, bb; unpack2(acc2[c2], a, bb);
        const int ch = c2 * 2;
        float r0 = fmaxf(a  * s_sc[ch]     + s_sh[ch],     0.f);
        float r1 = fmaxf(bb * s_sc[ch + 1] + s_sh[ch + 1], 0.f);
        e2 += s_w2[ch] * r0 + s_w2[ch + 1] * r1;
    }
    float sig = 1.f / (1.f + ex2f(-e2 * LOG2E));
    g_w[b * HW + p] = 1.f + beta[0] * sig;
}

// ================= kernel 2: QKV projections =================
// Q,K stored channel-major [b][c][n] (Q pre-scaled by log2e); Vw = (Wv x + bv)*w
// stored token-major [b][n][c].
__global__ __launch_bounds__(256) void qkv_kernel(
    const float* __restrict__ x,
    const float* __restrict__ Wq, const float* __restrict__ bq,
    const float* __restrict__ Wk, const float* __restrict__ bk,
    const float* __restrict__ Wv, const float* __restrict__ bv)
{
    __shared__ __align__(16) float xs[64 * 64];        // [c][n]
    __shared__ __align__(16) float WTq[32 * 64];       // [c_chunk][o]
    __shared__ __align__(16) float WTk[32 * 64];
    __shared__ __align__(16) float WTv[32 * 64];

    const int tid = threadIdx.x;
    const int b   = blockIdx.y;
    const int n0  = blockIdx.x * 64;

    for (int e = tid; e < 4096; e += 256) {
        int c = e >> 6, j = e & 63;
        xs[c * 64 + j] = x[(size_t)(b * 64 + c) * HW + n0 + j];
    }

    const int tn = tid & 15, to = tid >> 4;
    double aq[4][2], ak[4][2], av[4][2];
    #pragma unroll
    for (int i = 0; i < 4; i++) {
        aq[i][0] = aq[i][1] = 0.0; ak[i][0] = ak[i][1] = 0.0; av[i][0] = av[i][1] = 0.0;
    }

    for (int chunk = 0; chunk < 2; chunk++) {
        __syncthreads();
        for (int e = tid; e < 2048; e += 256) {
            int o = e & 63, c = e >> 6;
            WTq[c * 64 + o] = Wq[o * 64 + chunk * 32 + c];
            WTk[c * 64 + o] = Wk[o * 64 + chunk * 32 + c];
            WTv[c * 64 + o] = Wv[o * 64 + chunk * 32 + c];
        }
        __syncthreads();
        #pragma unroll 4
        for (int cc = 0; cc < 32; cc++) {
            const float4 xv = *(const float4*)&xs[(chunk * 32 + cc) * 64 + tn * 4];
            const double2 wq = *(const double2*)&WTq[cc * 64 + to * 4];
            const double2 wk = *(const double2*)&WTk[cc * 64 + to * 4];
            const double2 wv = *(const double2*)&WTv[cc * 64 + to * 4];
            double dn[4] = {dup2(xv.x), dup2(xv.y), dup2(xv.z), dup2(xv.w)};
            #pragma unroll
            for (int jn = 0; jn < 4; jn++) {
                ffma2(aq[jn][0], dn[jn], wq.x); ffma2(aq[jn][1], dn[jn], wq.y);
                ffma2(ak[jn][0], dn[jn], wk.x); ffma2(ak[jn][1], dn[jn], wk.y);
                ffma2(av[jn][0], dn[jn], wv.x); ffma2(av[jn][1], dn[jn], wv.y);
            }
        }
    }

    const int ob = to * 4;
    float bqv[4], bkv[4], bvv[4];
    #pragma unroll
    for (int io = 0; io < 4; io++) {
        bqv[io] = bq[ob + io]; bkv[io] = bk[ob + io]; bvv[io] = bv[ob + io];
    }
    #pragma unroll
    for (int jn = 0; jn < 4; jn++) {
        const int n = n0 + tn * 4 + jn;
        float q0,q1,q2,q3, k0,k1,k2,k3, v0,v1,v2,v3;
        unpack2(aq[jn][0], q0, q1); unpack2(aq[jn][1], q2, q3);
        unpack2(ak[jn][0], k0, k1); unpack2(ak[jn][1], k2, k3);
        unpack2(av[jn][0], v0, v1); unpack2(av[jn][1], v2, v3);
        const size_t base = ((size_t)(b * 64 + ob)) * HW + n;
        g_Qc[base           ] = (q0 + bqv[0]) * LOG2E;
        g_Qc[base +     HW  ] = (q1 + bqv[1]) * LOG2E;
        g_Qc[base + 2 * HW  ] = (q2 + bqv[2]) * LOG2E;
        g_Qc[base + 3 * HW  ] = (q3 + bqv[3]) * LOG2E;
        g_Kc[base           ] = k0 + bkv[0];
        g_Kc[base +     HW  ] = k1 + bkv[1];
        g_Kc[base + 2 * HW  ] = k2 + bkv[2];
        g_Kc[base + 3 * HW  ] = k3 + bkv[3];
        const float wnj = g_w[b * HW + n];
        float4 vo = make_float4((v0 + bvv[0]) * wnj, (v1 + bvv[1]) * wnj,
                                (v2 + bvv[2]) * wnj, (v3 + bvv[3]) * wnj);
        *(float4*)&g_Vw[((size_t)b * HW + n) * 64 + ob] = vo;
    }
}

// ================= kernel 3: flash attention (fused weight + L1 renorm) =====
// out[b,c,n] = gamma * (sum_m e^{s-m} w v) / (sum_m e^{s-m}|w|) + x[b,c,n]
__global__ __launch_bounds__(256, 1) void flash_kernel(
    const float* __restrict__ x, const float* __restrict__ gamma,
    float* __restrict__ out)
{
    extern __shared__ float sm[];
    float* QsT = sm;              // [64][128]
    float* KsT = sm + 8192;       // [64][128]
    float* Vs  = sm + 16384;      // [128][64]
    float* Ps  = sm + 24576;      // [128][128]
    float* aws = sm + 40960;      // [128]

    const int tid = threadIdx.x;
    const int b   = blockIdx.y;
    const int n0  = blockIdx.x * 128;
    const int tx  = tid & 15, ty = tid >> 4;

    const float* Qg = g_Qc + (size_t)b * 64 * HW;
    const float* Kg = g_Kc + (size_t)b * 64 * HW;
    const float* Vg = g_Vw + (size_t)b * HW * 64;

    for (int e = tid; e < 2048; e += 256) {
        int row = e >> 5, col = (e & 31) << 2;
        *(float4*)&QsT[row * 128 + col] =
            *(const float4*)(Qg + (size_t)row * HW + n0 + col);
    }

    double accO[8][2];
    float  mrow[8], drow[8];
    #pragma unroll
    for (int i = 0; i < 8; i++) { accO[i][0] = accO[i][1] = 0.0; mrow[i] = -1e30f; drow[i] = 0.f; }

    for (int t = 0; t < 32; t++) {
        const int m0 = t * 128;
        for (int e = tid; e < 2048; e += 256) {
            int row = e >> 5, col = (e & 31) << 2;
            *(float4*)&KsT[row * 128 + col] =
                *(const float4*)(Kg + (size_t)row * HW + m0 + col);
        }
        for (int e = tid; e < 2048; e += 256) {
            int row = e >> 4, col = (e & 15) << 2;
            *(float4*)&Vs[row * 64 + col] =
                *(const float4*)(Vg + (size_t)(m0 + row) * 64 + col);
        }
        if (tid < 128) aws[tid] = fabsf(g_w[b * HW + m0 + tid]);
        __syncthreads();

        // ---- S = (log2e*Q) K^T, 8x8 register tile on FFMA2 ----
        double accS[8][4];
        #pragma unroll
        for (int i = 0; i < 8; i++) { accS[i][0]=accS[i][1]=accS[i][2]=accS[i][3]=0.0; }
        #pragma unroll 8
        for (int c = 0; c < 64; c++) {
            const float4  qa  = *(const float4*) &QsT[c * 128 + ty * 8];
            const float4  qb  = *(const float4*) &QsT[c * 128 + ty * 8 + 4];
            const double2 k01 = *(const double2*)&KsT[c * 128 + tx * 8];
            const double2 k23 = *(const double2*)&KsT[c * 128 + tx * 8 + 4];
            const float qv[8] = {qa.x, qa.y, qa.z, qa.w, qb.x, qb.y, qb.z, qb.w};
            #pragma unroll
            for (int i = 0; i < 8; i++) {
                double dq = dup2(qv[i]);
                ffma2(accS[i][0], dq, k01.x);
                ffma2(accS[i][1], dq, k01.y);
                ffma2(accS[i][2], dq, k23.x);
                ffma2(accS[i][3], dq, k23.y);
            }
        }

        float awr[8];
        {
            const float4 a0 = *(const float4*)&aws[tx * 8];
            const float4 a1 = *(const float4*)&aws[tx * 8 + 4];
            awr[0]=a0.x; awr[1]=a0.y; awr[2]=a0.z; awr[3]=a0.w;
            awr[4]=a1.x; awr[5]=a1.y; awr[6]=a1.z; awr[7]=a1.w;
        }

        // ---- online softmax (state in registers, 16-lane shuffles) ----
        #pragma unroll
        for (int i = 0; i < 8; i++) {
            float s[8];
            unpack2(accS[i][0], s[0], s[1]);
            unpack2(accS[i][1], s[2], s[3]);
            unpack2(accS[i][2], s[4], s[5]);
            unpack2(accS[i][3], s[6], s[7]);
            float mx = s[0];
            #pragma unroll
            for (int j = 1; j < 8; j++) mx = fmaxf(mx, s[j]);
            #pragma unroll
            for (int off = 8; off >= 1; off >>= 1)
                mx = fmaxf(mx, __shfl_xor_sync(0xffffffffu, mx, off));
            const float mnew = fmaxf(mrow[i], mx);
            const float corr = ex2f(mrow[i] - mnew);
            mrow[i] = mnew;
            float p[8], rsum = 0.f;
            #pragma unroll
            for (int j = 0; j < 8; j++) { p[j] = ex2f(s[j] - mnew); rsum += p[j] * awr[j]; }
            #pragma unroll
            for (int off = 8; off >= 1; off >>= 1)
                rsum += __shfl_xor_sync(0xffffffffu, rsum, off);
            drow[i] = drow[i] * corr + rsum;
            const double dc = dup2(corr);
            accO[i][0] = fmul2(accO[i][0], dc);
            accO[i][1] = fmul2(accO[i][1], dc);
            float4 w0 = make_float4(p[0], p[1], p[2], p[3]);
            float4 w1 = make_float4(p[4], p[5], p[6], p[7]);
            *(float4*)&Ps[(ty * 8 + i) * 128 + tx * 8    ] = w0;
            *(float4*)&Ps[(ty * 8 + i) * 128 + tx * 8 + 4] = w1;
        }
        __syncthreads();

        // ---- O += P * Vw (8q x 4c tile on FFMA2) ----
        #pragma unroll 4
        for (int m = 0; m < 128; m++) {
            const double v0 = *(const double*)&Vs[m * 64 + tx * 4];
            const double v1 = *(const double*)&Vs[m * 64 + tx * 4 + 2];
            #pragma unroll
            for (int i = 0; i < 8; i++) {
                double dp = dup2(Ps[(ty * 8 + i) * 128 + m]);
                ffma2(accO[i][0], dp, v0);
                ffma2(accO[i][1], dp, v1);
            }
        }
        __syncthreads();
    }

    const float g0 = gamma[0];
    #pragma unroll
    for (int i = 0; i < 8; i++) {
        const float inv = 1.f / drow[i];
        float o0, o1, o2, o3;
        unpack2(accO[i][0], o0, o1);
        unpack2(accO[i][1], o2, o3);
        const int n  = n0 + ty * 8 + i;
        const int cb = tx * 4;
        const size_t base = ((size_t)(b * 64 + cb)) * HW + n;
        out[base         ] = g0 * o0 * inv + x[base         ];
        out[base +     HW] = g0 * o1 * inv + x[base +     HW];
        out[base + 2 * HW] = g0 * o2 * inv + x[base + 2 * HW];
        out[base + 3 * HW] = g0 * o3 * inv + x[base + 3 * HW];
    }
}

// ================= launch =================
extern "C" void kernel_launch(void* const* d_in, const int* in_sizes, int n_in,
                              void* d_out, int out_size)
{
    (void)in_sizes; (void)n_in; (void)out_size;
    const float* x       = (const float*)d_in[0];
    const float* Wq      = (const float*)d_in[1];
    const float* bq      = (const float*)d_in[2];
    const float* Wk      = (const float*)d_in[3];
    const float* bk      = (const float*)d_in[4];
    const float* Wv      = (const float*)d_in[5];
    const float* bv      = (const float*)d_in[6];
    const float* We1     = (const float*)d_in[7];
    const float* be1     = (const float*)d_in[8];
    const float* bn_w    = (const float*)d_in[9];
    const float* bn_b    = (const float*)d_in[10];
    const float* bn_mean = (const float*)d_in[11];
    const float* bn_var  = (const float*)d_in[12];
    const float* We2     = (const float*)d_in[13];
    const float* be2     = (const float*)d_in[14];
    const float* gamma   = (const float*)d_in[15];
    const float* beta    = (const float*)d_in[16];
    float* out = (float*)d_out;

    edge_kernel<<<dim3(32, NB), 128>>>(x, We1, be1, bn_w, bn_b, bn_mean, bn_var,
                                       We2, be2, beta);
    qkv_kernel<<<dim3(64, NB), 256>>>(x, Wq, bq, Wk, bk, Wv, bv);

    const int flash_smem = 41088 * 4;  // 164352 B
    cudaFuncSetAttribute(flash_kernel, cudaFuncAttributeMaxDynamicSharedMemorySize,
                         flash_smem);
    flash_kernel<<<dim3(32, NB), 256, flash_smem>>>(x, gamma, out);
}

// round 3
// speedup vs baseline: 1.0057x; 1.0057x over previous
#include <cuda_runtime.h>

#define HW    4096
#define NB    4
#define LOG2E 1.44269504088896340736f

// ---------------- scratch (device globals: allocation-free) ----------------
__device__ float g_Qc[NB * 64 * HW];   // [b][c][n], pre-scaled by log2e
__device__ float g_Kc[NB * 64 * HW];   // [b][c][n]
__device__ float g_Vw[NB * HW * 64];   // [b][n][c]  (w folded in)
__device__ float g_w [NB * HW];        // w[m] = 1 + beta*edge

// ---------------- f32x2 packed-FMA helpers (FFMA2) ----------------
__device__ __forceinline__ double dup2(float x) {
    double r; asm("mov.b64 %0, {%1,%1};" : "=d"(r) : "f"(x)); return r;
}
__device__ __forceinline__ void ffma2(double &d, double a, double b) {
    asm("fma.rn.f32x2 %0, %1, %2, %0;" : "+d"(d) : "d"(a), "d"(b));
}
__device__ __forceinline__ double fmul2(double a, double b) {
    double r; asm("mul.rn.f32x2 %0, %1, %2;" : "=d"(r) : "d"(a), "d"(b)); return r;
}
__device__ __forceinline__ void unpack2(double v, float &lo, float &hi) {
    asm("mov.b64 {%0,%1}, %2;" : "=f"(lo), "=f"(hi) : "d"(v));
}
__device__ __forceinline__ float ex2f(float x) {
    float r; asm("ex2.approx.f32 %0, %1;" : "=f"(r) : "f"(x)); return r;
}

// ================= kernel 1: edge detector -> g_w =================
// 3x3 conv (64->32) + folded BN + ReLU + 1x1 (32->1) + sigmoid
__global__ __launch_bounds__(128) void edge_kernel(
    const float* __restrict__ x,  const float* __restrict__ We1,
    const float* __restrict__ be1,
    const float* __restrict__ bn_w, const float* __restrict__ bn_b,
    const float* __restrict__ bn_mean, const float* __restrict__ bn_var,
    const float* __restrict__ We2, const float* __restrict__ be2,
    const float* __restrict__ beta)
{
    __shared__ __align__(16) float Wsh[32 * 9 * 32];   // [cc][k][ch] chunk
    __shared__ float s_sc[32], s_sh[32], s_w2[32];

    const int tid = threadIdx.x;
    const int b   = blockIdx.y;
    const int p   = blockIdx.x * 128 + tid;
    const int h   = p >> 6, w = p & 63;

    if (tid < 32) {
        float s = bn_w[tid] * rsqrtf(bn_var[tid] + 1e-5f);
        s_sc[tid] = s;
        s_sh[tid] = (be1[tid] - bn_mean[tid]) * s + bn_b[tid];
        s_w2[tid] = We2[tid];
    }

    double acc2[16];
    #pragma unroll
    for (int i = 0; i < 16; i++) acc2[i] = 0.0;

    for (int chunk = 0; chunk < 2; chunk++) {
        __syncthreads();
        for (int e = tid; e < 32 * 9 * 32; e += 128) {
            int ch = e & 31, rest = e >> 5;
            int k = rest % 9, cc = rest / 9;
            Wsh[e] = We1[((ch * 64) + (chunk * 32 + cc)) * 9 + k];
        }
        __syncthreads();
        const float* xb = x + (size_t)(b * 64 + chunk * 32) * HW;
        for (int cc = 0; cc < 32; cc++) {
            const float* xc = xb + cc * HW;
            #pragma unroll
            for (int k = 0; k < 9; k++) {
                const int dy = k / 3 - 1, dx = k % 3 - 1;
                const int hh = h + dy, ww = w + dx;
                float xv = 0.f;
                if (hh >= 0 && hh < 64 && ww >= 0 && ww < 64) xv = xc[hh * 64 + ww];
                double dv = dup2(xv);
                const double* wrow = (const double*)&Wsh[(cc * 9 + k) * 32];
                #pragma unroll
                for (int c2 = 0; c2 < 16; c2++) ffma2(acc2[c2], dv, wrow[c2]);
            }
        }
    }

    float e2 = be2[0];
    #pragma unroll
    for (int c2 = 0; c2 < 16; c2++) {
        float a, bb; unpack2(acc2[c2], a, bb);
        const int ch = c2 * 2;
        float r0 = fmaxf(a  * s_sc[ch]     + s_sh[ch],     0.f);
        float r1 = fmaxf(bb * s_sc[ch + 1] + s_sh[ch + 1], 0.f);
        e2 += s_w2[ch] * r0 + s_w2[ch + 1] * r1;
    }
    float sig = 1.f / (1.f + ex2f(-e2 * LOG2E));
    g_w[b * HW + p] = 1.f + beta[0] * sig;
}

// ================= kernel 2: QKV projections =================
// Q,K stored channel-major [b][c][n] (Q pre-scaled by log2e); Vw = (Wv x + bv)*w
// stored token-major [b][n][c].
__global__ __launch_bounds__(256) void qkv_kernel(
    const float* __restrict__ x,
    const float* __restrict__ Wq, const float* __restrict__ bq,
    const float* __restrict__ Wk, const float* __restrict__ bk,
    const float* __restrict__ Wv, const float* __restrict__ bv)
{
    __shared__ __align__(16) float xs[64 * 64];        // [c][n]
    __shared__ __align__(16) float WTq[32 * 64];       // [c_chunk][o]
    __shared__ __align__(16) float WTk[32 * 64];
    __shared__ __align__(16) float WTv[32 * 64];

    const int tid = threadIdx.x;
    const int b   = blockIdx.y;
    const int n0  = blockIdx.x * 64;

    for (int e = tid; e < 4096; e += 256) {
        int c = e >> 6, j = e & 63;
        xs[c * 64 + j] = x[(size_t)(b * 64 + c) * HW + n0 + j];
    }

    const int tn = tid & 15, to = tid >> 4;
    double aq[4][2], ak[4][2], av[4][2];
    #pragma unroll
    for (int i = 0; i < 4; i++) {
        aq[i][0] = aq[i][1] = 0.0; ak[i][0] = ak[i][1] = 0.0; av[i][0] = av[i][1] = 0.0;
    }

    for (int chunk = 0; chunk < 2; chunk++) {
        __syncthreads();
        for (int e = tid; e < 2048; e += 256) {
            int o = e & 63, c = e >> 6;
            WTq[c * 64 + o] = Wq[o * 64 + chunk * 32 + c];
            WTk[c * 64 + o] = Wk[o * 64 + chunk * 32 + c];
            WTv[c * 64 + o] = Wv[o * 64 + chunk * 32 + c];
        }
        __syncthreads();
        #pragma unroll 4
        for (int cc = 0; cc < 32; cc++) {
            const float4 xv = *(const float4*)&xs[(chunk * 32 + cc) * 64 + tn * 4];
            const double2 wq = *(const double2*)&WTq[cc * 64 + to * 4];
            const double2 wk = *(const double2*)&WTk[cc * 64 + to * 4];
            const double2 wv = *(const double2*)&WTv[cc * 64 + to * 4];
            double dn[4] = {dup2(xv.x), dup2(xv.y), dup2(xv.z), dup2(xv.w)};
            #pragma unroll
            for (int jn = 0; jn < 4; jn++) {
                ffma2(aq[jn][0], dn[jn], wq.x); ffma2(aq[jn][1], dn[jn], wq.y);
                ffma2(ak[jn][0], dn[jn], wk.x); ffma2(ak[jn][1], dn[jn], wk.y);
                ffma2(av[jn][0], dn[jn], wv.x); ffma2(av[jn][1], dn[jn], wv.y);
            }
        }
    }

    const int ob = to * 4;
    float bqv[4], bkv[4], bvv[4];
    #pragma unroll
    for (int io = 0; io < 4; io++) {
        bqv[io] = bq[ob + io]; bkv[io] = bk[ob + io]; bvv[io] = bv[ob + io];
    }
    #pragma unroll
    for (int jn = 0; jn < 4; jn++) {
        const int n = n0 + tn * 4 + jn;
        float q0,q1,q2,q3, k0,k1,k2,k3, v0,v1,v2,v3;
        unpack2(aq[jn][0], q0, q1); unpack2(aq[jn][1], q2, q3);
        unpack2(ak[jn][0], k0, k1); unpack2(ak[jn][1], k2, k3);
        unpack2(av[jn][0], v0, v1); unpack2(av[jn][1], v2, v3);
        const size_t base = ((size_t)(b * 64 + ob)) * HW + n;
        g_Qc[base           ] = (q0 + bqv[0]) * LOG2E;
        g_Qc[base +     HW  ] = (q1 + bqv[1]) * LOG2E;
        g_Qc[base + 2 * HW  ] = (q2 + bqv[2]) * LOG2E;
        g_Qc[base + 3 * HW  ] = (q3 + bqv[3]) * LOG2E;
        g_Kc[base           ] = k0 + bkv[0];
        g_Kc[base +     HW  ] = k1 + bkv[1];
        g_Kc[base + 2 * HW  ] = k2 + bkv[2];
        g_Kc[base + 3 * HW  ] = k3 + bkv[3];
        const float wnj = g_w[b * HW + n];
        float4 vo = make_float4((v0 + bvv[0]) * wnj, (v1 + bvv[1]) * wnj,
                                (v2 + bvv[2]) * wnj, (v3 + bvv[3]) * wnj);
        *(float4*)&g_Vw[((size_t)b * HW + n) * 64 + ob] = vo;
    }
}

// ================= kernel 3: flash attention (fused weight + L1 renorm) =====
// out[b,c,n] = gamma * (sum_m e^{s-m} w v) / (sum_m e^{s-m}|w|) + x[b,c,n]
__global__ __launch_bounds__(256, 1) void flash_kernel(
    const float* __restrict__ x, const float* __restrict__ gamma,
    float* __restrict__ out)
{
    extern __shared__ float sm[];
    float* QsT = sm;              // [64][128]
    float* KsT = sm + 8192;       // [64][128]
    float* Vs  = sm + 16384;      // [128][64]
    float* Ps  = sm + 24576;      // [128][128]
    float* aws = sm + 40960;      // [128]

    const int tid = threadIdx.x;
    const int b   = blockIdx.y;
    const int n0  = blockIdx.x * 128;
    const int tx  = tid & 15, ty = tid >> 4;

    const float* Qg = g_Qc + (size_t)b * 64 * HW;
    const float* Kg = g_Kc + (size_t)b * 64 * HW;
    const float* Vg = g_Vw + (size_t)b * HW * 64;

    for (int e = tid; e < 2048; e += 256) {
        int row = e >> 5, col = (e & 31) << 2;
        *(float4*)&QsT[row * 128 + col] =
            *(const float4*)(Qg + (size_t)row * HW + n0 + col);
    }

    double accO[8][2];
    float  mrow[8], drow[8];
    #pragma unroll
    for (int i = 0; i < 8; i++) { accO[i][0] = accO[i][1] = 0.0; mrow[i] = -1e30f; drow[i] = 0.f; }

    for (int t = 0; t < 32; t++) {
        const int m0 = t * 128;
        for (int e = tid; e < 2048; e += 256) {
            int row = e >> 5, col = (e & 31) << 2;
            *(float4*)&KsT[row * 128 + col] =
                *(const float4*)(Kg + (size_t)row * HW + m0 + col);
        }
        for (int e = tid; e < 2048; e += 256) {
            int row = e >> 4, col = (e & 15) << 2;
            *(float4*)&Vs[row * 64 + col] =
                *(const float4*)(Vg + (size_t)(m0 + row) * 64 + col);
        }
        if (tid < 128) aws[tid] = fabsf(g_w[b * HW + m0 + tid]);
        __syncthreads();

        // ---- S = (log2e*Q) K^T, 8x8 register tile on FFMA2 ----
        double accS[8][4];
        #pragma unroll
        for (int i = 0; i < 8; i++) { accS[i][0]=accS[i][1]=accS[i][2]=accS[i][3]=0.0; }
        #pragma unroll 8
        for (int c = 0; c < 64; c++) {
            const float4  qa  = *(const float4*) &QsT[c * 128 + ty * 8];
            const float4  qb  = *(const float4*) &QsT[c * 128 + ty * 8 + 4];
            const double2 k01 = *(const double2*)&KsT[c * 128 + tx * 8];
            const double2 k23 = *(const double2*)&KsT[c * 128 + tx * 8 + 4];
            const float qv[8] = {qa.x, qa.y, qa.z, qa.w, qb.x, qb.y, qb.z, qb.w};
            #pragma unroll
            for (int i = 0; i < 8; i++) {
                double dq = dup2(qv[i]);
                ffma2(accS[i][0], dq, k01.x);
                ffma2(accS[i][1], dq, k01.y);
                ffma2(accS[i][2], dq, k23.x);
                ffma2(accS[i][3], dq, k23.y);
            }
        }

        float awr[8];
        {
            const float4 a0 = *(const float4*)&aws[tx * 8];
            const float4 a1 = *(const float4*)&aws[tx * 8 + 4];
            awr[0]=a0.x; awr[1]=a0.y; awr[2]=a0.z; awr[3]=a0.w;
            awr[4]=a1.x; awr[5]=a1.y; awr[6]=a1.z; awr[7]=a1.w;
        }

        // ---- online softmax (state in registers, 16-lane shuffles) ----
        #pragma unroll
        for (int i = 0; i < 8; i++) {
            float s[8];
            unpack2(accS[i][0], s[0], s[1]);
            unpack2(accS[i][1], s[2], s[3]);
            unpack2(accS[i][2], s[4], s[5]);
            unpack2(accS[i][3], s[6], s[7]);
            float mx = s[0];
            #pragma unroll
            for (int j = 1; j < 8; j++) mx = fmaxf(mx, s[j]);
            #pragma unroll
            for (int off = 8; off >= 1; off >>= 1)
                mx = fmaxf(mx, __shfl_xor_sync(0xffffffffu, mx, off));
            const float mnew = fmaxf(mrow[i], mx);
            const float corr = ex2f(mrow[i] - mnew);
            mrow[i] = mnew;
            float p[8], rsum = 0.f;
            #pragma unroll
            for (int j = 0; j < 8; j++) { p[j] = ex2f(s[j] - mnew); rsum += p[j] * awr[j]; }
            #pragma unroll
            for (int off = 8; off >= 1; off >>= 1)
                rsum += __shfl_xor_sync(0xffffffffu, rsum, off);
            drow[i] = drow[i] * corr + rsum;
            const double dc = dup2(corr);
            accO[i][0] = fmul2(accO[i][0], dc);
            accO[i][1] = fmul2(accO[i][1], dc);
            float4 w0 = make_float4(p[0], p[1], p[2], p[3]);
            float4 w1 = make_float4(p[4], p[5], p[6], p[7]);
            *(float4*)&Ps[(ty * 8 + i) * 128 + tx * 8    ] = w0;
            *(float4*)&Ps[(ty * 8 + i) * 128 + tx * 8 + 4] = w1;
        }
        __syncthreads();

        // ---- O += P * Vw (8q x 4c tile on FFMA2) ----
        #pragma unroll 4
        for (int m = 0; m < 128; m++) {
            const double v0 = *(const double*)&Vs[m * 64 + tx * 4];
            const double v1 = *(const double*)&Vs[m * 64 + tx * 4 + 2];
            #pragma unroll
            for (int i = 0; i < 8; i++) {
                double dp = dup2(Ps[(ty * 8 + i) * 128 + m]);
                ffma2(accO[i][0], dp, v0);
                ffma2(accO[i][1], dp, v1);
            }
        }
        __syncthreads();
    }

    const float g0 = gamma[0];
    #pragma unroll
    for (int i = 0; i < 8; i++) {
        const float inv = 1.f / drow[i];
        float o0, o1, o2, o3;
        unpack2(accO[i][0], o0, o1);
        unpack2(accO[i][1], o2, o3);
        const int n  = n0 + ty * 8 + i;
        const int cb = tx * 4;
        const size_t base = ((size_t)(b * 64 + cb)) * HW + n;
        out[base         ] = g0 * o0 * inv + x[base         ];
        out[base +     HW] = g0 * o1 * inv + x[base +     HW];
        out[base + 2 * HW] = g0 * o2 * inv + x[base + 2 * HW];
        out[base + 3 * HW] = g0 * o3 * inv + x[base + 3 * HW];
    }
}

// ================= launch =================
extern "C" void kernel_launch(void* const* d_in, const int* in_sizes, int n_in,
                              void* d_out, int out_size)
{
    (void)in_sizes; (void)n_in; (void)out_size;
    const float* x       = (const float*)d_in[0];
    const float* Wq      = (const float*)d_in[1];
    const float* bq      = (const float*)d_in[2];
    const float* Wk      = (const float*)d_in[3];
    const float* bk      = (const float*)d_in[4];
    const float* Wv      = (const float*)d_in[5];
    const float* bv      = (const float*)d_in[6];
    const float* We1     = (const float*)d_in[7];
    const float* be1     = (const float*)d_in[8];
    const float* bn_w    = (const float*)d_in[9];
    const float* bn_b    = (const float*)d_in[10];
    const float* bn_mean = (const float*)d_in[11];
    const float* bn_var  = (const float*)d_in[12];
    const float* We2     = (const float*)d_in[13];
    const float* be2     = (const float*)d_in[14];
    const float* gamma   = (const float*)d_in[15];
    const float* beta    = (const float*)d_in[16];
    float* out = (float*)d_out;

    edge_kernel<<<dim3(32, NB), 128>>>(x, We1, be1, bn_w, bn_b, bn_mean, bn_var,
                                       We2, be2, beta);
    qkv_kernel<<<dim3(64, NB), 256>>>(x, Wq, bq, Wk, bk, Wv, bv);

    const int flash_smem = 41088 * 4;  // 164352 B
    cudaFuncSetAttribute(flash_kernel, cudaFuncAttributeMaxDynamicSharedMemorySize,
                         flash_smem);
    flash_kernel<<<dim3(32, NB), 256, flash_smem>>>(x, gamma, out);
}

// round 5
// speedup vs baseline: 1.8336x; 1.8231x over previous
#include <cuda_runtime.h>
#include <cuda_bf16.h>
#include <cstdint>

#define HW    4096
#define NB    4
#define LOG2E 1.44269504088896340736f

// ---------------- scratch (device globals: allocation-free) ----------------
__device__ __nv_bfloat16 g_Qh[NB * HW * 64];   // [b][n][c] hi, pre-scaled by log2e
__device__ __nv_bfloat16 g_Ql[NB * HW * 64];   // [b][n][c] lo
__device__ __nv_bfloat16 g_Kh[NB * HW * 64];   // [b][n][c] hi
__device__ __nv_bfloat16 g_Kl[NB * HW * 64];   // [b][n][c] lo
__device__ __nv_bfloat16 g_Vb[NB * 64 * HW];   // [b][c][m]  (w folded in), bf16
__device__ float         g_w [NB * HW];        // w[m] = 1 + beta*edge

// ---------------- f32x2 packed-FMA helpers ----------------
__device__ __forceinline__ double dup2(float x) {
    double r; asm("mov.b64 %0, {%1,%1};" : "=d"(r) : "f"(x)); return r;
}
__device__ __forceinline__ void ffma2(double &d, double a, double b) {
    asm("fma.rn.f32x2 %0, %1, %2, %0;" : "+d"(d) : "d"(a), "d"(b));
}
__device__ __forceinline__ void unpack2(double v, float &lo, float &hi) {
    asm("mov.b64 {%0,%1}, %2;" : "=f"(lo), "=f"(hi) : "d"(v));
}
__device__ __forceinline__ float ex2f(float x) {
    float r; asm("ex2.approx.f32 %0, %1;" : "=f"(r) : "f"(x)); return r;
}
__device__ __forceinline__ uint32_t bf16x2_pack(float lo, float hi) {
    uint32_t r; asm("cvt.rn.bf16x2.f32 %0, %1, %2;" : "=r"(r) : "f"(hi), "f"(lo));
    return r;
}
__device__ __forceinline__ uint32_t smem_u32(const void* p) {
    uint32_t a;
    asm("{ .reg .u64 t; cvta.to.shared.u64 t, %1; cvt.u32.u64 %0, t; }"
        : "=r"(a) : "l"(p));
    return a;
}

#define SW128(o) ((o) ^ (((o) >> 3) & 0x70))

// ---------------- mma.sync / ldmatrix (sm_80+ path; works on compute_103) ----
#define LDMX4(r, addr) \
    asm volatile("ldmatrix.sync.aligned.m8n8.x4.shared.b16 {%0,%1,%2,%3}, [%4];" \
        : "=r"((r)[0]), "=r"((r)[1]), "=r"((r)[2]), "=r"((r)[3]) : "r"(addr))

#define MMA16816(d, a, b0, b1) \
    asm volatile("mma.sync.aligned.m16n8k16.row.col.f32.bf16.bf16.f32 " \
        "{%0,%1,%2,%3},{%4,%5,%6,%7},{%8,%9},{%0,%1,%2,%3};" \
        : "+f"((d)[0]), "+f"((d)[1]), "+f"((d)[2]), "+f"((d)[3]) \
        : "r"((a)[0]), "r"((a)[1]), "r"((a)[2]), "r"((a)[3]), "r"(b0), "r"(b1))

// ================= kernel 1: edge detector -> g_w =================
__global__ __launch_bounds__(256) void edge_kernel(
    const float* __restrict__ x,  const float* __restrict__ We1,
    const float* __restrict__ be1,
    const float* __restrict__ bn_w, const float* __restrict__ bn_b,
    const float* __restrict__ bn_mean, const float* __restrict__ bn_var,
    const float* __restrict__ We2, const float* __restrict__ be2,
    const float* __restrict__ beta)
{
    __shared__ __align__(16) float Wsh[32 * 9 * 32];
    __shared__ float s_sc[32], s_sh[32], s_w2[32];

    const int tid = threadIdx.x;
    const int b   = blockIdx.y;
    const int p   = blockIdx.x * 256 + tid;
    const int h   = p >> 6, w = p & 63;

    if (tid < 32) {
        float s = bn_w[tid] * rsqrtf(bn_var[tid] + 1e-5f);
        s_sc[tid] = s;
        s_sh[tid] = (be1[tid] - bn_mean[tid]) * s + bn_b[tid];
        s_w2[tid] = We2[tid];
    }

    bool ok[9]; int off[9];
    #pragma unroll
    for (int k = 0; k < 9; k++) {
        const int dy = k / 3 - 1, dx = k % 3 - 1;
        const int hh = h + dy, ww = w + dx;
        ok[k]  = (hh >= 0 && hh < 64 && ww >= 0 && ww < 64);
        off[k] = hh * 64 + ww;
    }

    double acc2[16];
    #pragma unroll
    for (int i = 0; i < 16; i++) acc2[i] = 0.0;

    for (int chunk = 0; chunk < 2; chunk++) {
        __syncthreads();
        for (int e = tid; e < 32 * 9 * 32; e += 256) {
            int ch = e & 31, rest = e >> 5;
            int k = rest % 9, cc = rest / 9;
            Wsh[e] = We1[((ch * 64) + (chunk * 32 + cc)) * 9 + k];
        }
        __syncthreads();
        const float* xb = x + (size_t)(b * 64 + chunk * 32) * HW;
        for (int cc = 0; cc < 32; cc++) {
            const float* xc = xb + cc * HW;
            float xv[9];
            #pragma unroll
            for (int k = 0; k < 9; k++) xv[k] = ok[k] ? xc[off[k]] : 0.f;
            #pragma unroll
            for (int k = 0; k < 9; k++) {
                double dv = dup2(xv[k]);
                const double* wrow = (const double*)&Wsh[(cc * 9 + k) * 32];
                #pragma unroll
                for (int c2 = 0; c2 < 16; c2++) ffma2(acc2[c2], dv, wrow[c2]);
            }
        }
    }

    float e2 = be2[0];
    #pragma unroll
    for (int c2 = 0; c2 < 16; c2++) {
        float a, bb; unpack2(acc2[c2], a, bb);
        const int ch = c2 * 2;
        float r0 = fmaxf(a  * s_sc[ch]     + s_sh[ch],     0.f);
        float r1 = fmaxf(bb * s_sc[ch + 1] + s_sh[ch + 1], 0.f);
        e2 += s_w2[ch] * r0 + s_w2[ch + 1] * r1;
    }
    float sig = 1.f / (1.f + ex2f(-e2 * LOG2E));
    g_w[b * HW + p] = 1.f + beta[0] * sig;
}

// ================= kernel 2: QKV projections -> bf16 hi/lo =================
__global__ __launch_bounds__(256) void qkv_kernel(
    const float* __restrict__ x,
    const float* __restrict__ Wq, const float* __restrict__ bq,
    const float* __restrict__ Wk, const float* __restrict__ bk,
    const float* __restrict__ Wv, const float* __restrict__ bv)
{
    __shared__ __align__(16) float xs[64 * 64];
    __shared__ __align__(16) float WTq[32 * 64];
    __shared__ __align__(16) float WTk[32 * 64];
    __shared__ __align__(16) float WTv[32 * 64];

    const int tid = threadIdx.x;
    const int b   = blockIdx.y;
    const int n0  = blockIdx.x * 64;

    for (int e = tid; e < 4096; e += 256) {
        int c = e >> 6, j = e & 63;
        xs[c * 64 + j] = x[(size_t)(b * 64 + c) * HW + n0 + j];
    }

    const int tn = tid & 15, to = tid >> 4;
    double aq[4][2], ak[4][2], av[4][2];
    #pragma unroll
    for (int i = 0; i < 4; i++) {
        aq[i][0] = aq[i][1] = 0.0; ak[i][0] = ak[i][1] = 0.0; av[i][0] = av[i][1] = 0.0;
    }

    for (int chunk = 0; chunk < 2; chunk++) {
        __syncthreads();
        for (int e = tid; e < 2048; e += 256) {
            int o = e & 63, c = e >> 6;
            WTq[c * 64 + o] = Wq[o * 64 + chunk * 32 + c];
            WTk[c * 64 + o] = Wk[o * 64 + chunk * 32 + c];
            WTv[c * 64 + o] = Wv[o * 64 + chunk * 32 + c];
        }
        __syncthreads();
        #pragma unroll 4
        for (int cc = 0; cc < 32; cc++) {
            const float4 xv = *(const float4*)&xs[(chunk * 32 + cc) * 64 + tn * 4];
            const double2 wq = *(const double2*)&WTq[cc * 64 + to * 4];
            const double2 wk = *(const double2*)&WTk[cc * 64 + to * 4];
            const double2 wv = *(const double2*)&WTv[cc * 64 + to * 4];
            double dn[4] = {dup2(xv.x), dup2(xv.y), dup2(xv.z), dup2(xv.w)};
            #pragma unroll
            for (int jn = 0; jn < 4; jn++) {
                ffma2(aq[jn][0], dn[jn], wq.x); ffma2(aq[jn][1], dn[jn], wq.y);
                ffma2(ak[jn][0], dn[jn], wk.x); ffma2(ak[jn][1], dn[jn], wk.y);
                ffma2(av[jn][0], dn[jn], wv.x); ffma2(av[jn][1], dn[jn], wv.y);
            }
        }
    }

    const int ob = to * 4;
    float bqv[4], bkv[4], bvv[4];
    #pragma unroll
    for (int io = 0; io < 4; io++) {
        bqv[io] = bq[ob + io]; bkv[io] = bk[ob + io]; bvv[io] = bv[ob + io];
    }
    #pragma unroll
    for (int jn = 0; jn < 4; jn++) {
        const int n = n0 + tn * 4 + jn;
        float qf[4], kf[4], vf[4];
        unpack2(aq[jn][0], qf[0], qf[1]); unpack2(aq[jn][1], qf[2], qf[3]);
        unpack2(ak[jn][0], kf[0], kf[1]); unpack2(ak[jn][1], kf[2], kf[3]);
        unpack2(av[jn][0], vf[0], vf[1]); unpack2(av[jn][1], vf[2], vf[3]);
        const float wnj = g_w[b * HW + n];
        __nv_bfloat16 qh[4], ql[4], kh[4], kl[4];
        #pragma unroll
        for (int io = 0; io < 4; io++) {
            float q = (qf[io] + bqv[io]) * LOG2E;
            float k = kf[io] + bkv[io];
            qh[io] = __float2bfloat16(q);
            ql[io] = __float2bfloat16(q - __bfloat162float(qh[io]));
            kh[io] = __float2bfloat16(k);
            kl[io] = __float2bfloat16(k - __bfloat162float(kh[io]));
            g_Vb[((size_t)(b * 64 + ob + io)) * HW + n] =
                __float2bfloat16((vf[io] + bvv[io]) * wnj);
        }
        const size_t base = ((size_t)(b * HW + n)) * 64 + ob;
        *(__nv_bfloat162*)&g_Qh[base]     = __nv_bfloat162(qh[0], qh[1]);
        *(__nv_bfloat162*)&g_Qh[base + 2] = __nv_bfloat162(qh[2], qh[3]);
        *(__nv_bfloat162*)&g_Ql[base]     = __nv_bfloat162(ql[0], ql[1]);
        *(__nv_bfloat162*)&g_Ql[base + 2] = __nv_bfloat162(ql[2], ql[3]);
        *(__nv_bfloat162*)&g_Kh[base]     = __nv_bfloat162(kh[0], kh[1]);
        *(__nv_bfloat162*)&g_Kh[base + 2] = __nv_bfloat162(kh[2], kh[3]);
        *(__nv_bfloat162*)&g_Kl[base]     = __nv_bfloat162(kl[0], kl[1]);
        *(__nv_bfloat162*)&g_Kl[base + 2] = __nv_bfloat162(kl[2], kl[3]);
    }
}

// ================= kernel 3: mma.sync flash attention =================
// smem (bytes):
#define OFF_QH 0            // 16KB  [128 tok][64c] bf16 SW128
#define OFF_QL 16384        // 16KB
#define OFF_K  32768        // 2 bufs * (KH 16KB + KL 16KB) = 64KB
#define OFF_V  98304        // 2 bufs * 16KB ([half_m][64c][64m] bf16, SW128)
#define OFF_AW 131072       // 2 bufs * 128 f32
#define SMEM_BYTES 132096

__global__ __launch_bounds__(256, 1) void flash_kernel(
    const float* __restrict__ x, const float* __restrict__ gamma,
    float* __restrict__ out)
{
    extern __shared__ char smem[];
    const uint32_t sbase = smem_u32(smem);
    const int tid  = threadIdx.x;
    const int lane = tid & 31, wid = tid >> 5;
    const int g    = lane >> 2;          // row within 8
    const int u    = lane & 3;           // col pair selector
    const int q0w  = wid * 16;           // this warp's q rows
    const int b    = blockIdx.y;
    const int n0   = blockIdx.x * 128;

    // ---- load Q (hi/lo) + tile 0 ----
    {
        const uint4* Qhg = (const uint4*)(g_Qh + ((size_t)(b * HW + n0)) * 64);
        const uint4* Qlg = (const uint4*)(g_Ql + ((size_t)(b * HW + n0)) * 64);
        for (int e = tid; e < 1024; e += 256) {
            int r = e >> 3, c8 = e & 7;
            uint32_t o = SW128(r * 128 + c8 * 16);
            *(uint4*)(smem + OFF_QH + o) = Qhg[e];
            *(uint4*)(smem + OFF_QL + o) = Qlg[e];
        }
        const uint4* KHg = (const uint4*)(g_Kh + ((size_t)(b * HW)) * 64);
        const uint4* KLg = (const uint4*)(g_Kl + ((size_t)(b * HW)) * 64);
        for (int e = tid; e < 1024; e += 256) {
            int r = e >> 3, c8 = e & 7;
            uint32_t o = SW128(r * 128 + c8 * 16);
            *(uint4*)(smem + OFF_K + o)         = KHg[e];
            *(uint4*)(smem + OFF_K + 16384 + o) = KLg[e];
        }
        const __nv_bfloat16* Vg = g_Vb + (size_t)b * 64 * HW;
        for (int e = tid; e < 1024; e += 256) {
            int c = e >> 4, j8 = e & 15;
            uint4 val = *(const uint4*)(Vg + (size_t)c * HW + j8 * 8);
            *(uint4*)(smem + OFF_V + (j8 >> 3) * 8192 +
                      SW128(c * 128 + (j8 & 7) * 16)) = val;
        }
        if (tid < 128) *(float*)(smem + OFF_AW + tid * 4) = fabsf(g_w[b * HW + tid]);
    }
    __syncthreads();

    // ---- Q fragments (persistent): a-frag per k-step, hi and lo ----
    uint32_t qh[4][4], ql[4][4];
    {
        const int row = q0w + (lane & 15);
        #pragma unroll
        for (int ks = 0; ks < 4; ks++) {
            const uint32_t cb = ks * 32 + (lane >> 4) * 16;
            LDMX4(qh[ks], sbase + OFF_QH + SW128(row * 128 + cb));
            LDMX4(ql[ks], sbase + OFF_QL + SW128(row * 128 + cb));
        }
    }

    float o[8][4];
    #pragma unroll
    for (int ct = 0; ct < 8; ct++)
        o[ct][0] = o[ct][1] = o[ct][2] = o[ct][3] = 0.f;
    float mrow0 = -1e30f, mrow1 = -1e30f, den0 = 0.f, den1 = 0.f;

    for (int t = 0; t < 32; t++) {
        const int buf = t & 1;

        // ---- load tile t+1 into the other buffer ----
        if (t < 31) {
            const int m1 = (t + 1) * 128, nb = buf ^ 1;
            const uint4* KHg = (const uint4*)(g_Kh + ((size_t)(b * HW + m1)) * 64);
            const uint4* KLg = (const uint4*)(g_Kl + ((size_t)(b * HW + m1)) * 64);
            char* kb = smem + OFF_K + nb * 32768;
            for (int e = tid; e < 1024; e += 256) {
                int r = e >> 3, c8 = e & 7;
                uint32_t oo = SW128(r * 128 + c8 * 16);
                *(uint4*)(kb + oo)         = KHg[e];
                *(uint4*)(kb + 16384 + oo) = KLg[e];
            }
            const __nv_bfloat16* Vg = g_Vb + (size_t)b * 64 * HW + m1;
            char* vb = smem + OFF_V + nb * 16384;
            for (int e = tid; e < 1024; e += 256) {
                int c = e >> 4, j8 = e & 15;
                uint4 val = *(const uint4*)(Vg + (size_t)c * HW + j8 * 8);
                *(uint4*)(vb + (j8 >> 3) * 8192 +
                          SW128(c * 128 + (j8 & 7) * 16)) = val;
            }
            if (tid < 128)
                *(float*)(smem + OFF_AW + nb * 512 + tid * 4) =
                    fabsf(g_w[b * HW + m1 + tid]);
        }

        const uint32_t kh_b = sbase + OFF_K + buf * 32768;
        const uint32_t kl_b = kh_b + 16384;
        const float*   awp  = (const float*)(smem + OFF_AW + buf * 512);

        #pragma unroll
        for (int sub = 0; sub < 2; sub++) {
            // ---- S = QK^T for 64 keys (8 n-tiles), hi/lo 3-pass ----
            float s[8][4];
            #pragma unroll
            for (int i = 0; i < 8; i++)
                s[i][0] = s[i][1] = s[i][2] = s[i][3] = 0.f;

            #pragma unroll
            for (int i = 0; i < 8; i++) {
                const int nt = sub * 8 + i;
                const uint32_t roff = (nt * 8 + (lane & 7)) * 128 + (lane >> 3) * 16;
                uint32_t bh[8], bl[8];
                LDMX4(bh,     kh_b + SW128(roff));
                LDMX4(bh + 4, kh_b + SW128(roff + 64));
                LDMX4(bl,     kl_b + SW128(roff));
                LDMX4(bl + 4, kl_b + SW128(roff + 64));
                #pragma unroll
                for (int ks = 0; ks < 4; ks++) {
                    MMA16816(s[i], qh[ks], bh[2 * ks], bh[2 * ks + 1]);
                    MMA16816(s[i], qh[ks], bl[2 * ks], bl[2 * ks + 1]);
                    MMA16816(s[i], ql[ks], bh[2 * ks], bh[2 * ks + 1]);
                }
            }

            // ---- online softmax (quad-local) ----
            float mx0 = s[0][0], mx1 = s[0][2];
            #pragma unroll
            for (int i = 0; i < 8; i++) {
                mx0 = fmaxf(mx0, fmaxf(s[i][0], s[i][1]));
                mx1 = fmaxf(mx1, fmaxf(s[i][2], s[i][3]));
            }
            mx0 = fmaxf(mx0, __shfl_xor_sync(0xffffffffu, mx0, 1));
            mx0 = fmaxf(mx0, __shfl_xor_sync(0xffffffffu, mx0, 2));
            mx1 = fmaxf(mx1, __shfl_xor_sync(0xffffffffu, mx1, 1));
            mx1 = fmaxf(mx1, __shfl_xor_sync(0xffffffffu, mx1, 2));

            const float mn0 = fmaxf(mrow0, mx0), mn1 = fmaxf(mrow1, mx1);
            const float cr0 = ex2f(mrow0 - mn0), cr1 = ex2f(mrow1 - mn1);
            mrow0 = mn0; mrow1 = mn1;

            float ws0 = 0.f, ws1 = 0.f;
            #pragma unroll
            for (int i = 0; i < 8; i++) {
                const float2 aw = *(const float2*)&awp[sub * 64 + i * 8 + 2 * u];
                s[i][0] = ex2f(s[i][0] - mn0);
                s[i][1] = ex2f(s[i][1] - mn0);
                s[i][2] = ex2f(s[i][2] - mn1);
                s[i][3] = ex2f(s[i][3] - mn1);
                ws0 += s[i][0] * aw.x + s[i][1] * aw.y;
                ws1 += s[i][2] * aw.x + s[i][3] * aw.y;
            }
            ws0 += __shfl_xor_sync(0xffffffffu, ws0, 1);
            ws0 += __shfl_xor_sync(0xffffffffu, ws0, 2);
            ws1 += __shfl_xor_sync(0xffffffffu, ws1, 1);
            ws1 += __shfl_xor_sync(0xffffffffu, ws1, 2);
            den0 = den0 * cr0 + ws0;
            den1 = den1 * cr1 + ws1;

            #pragma unroll
            for (int ct = 0; ct < 8; ct++) {
                o[ct][0] *= cr0; o[ct][1] *= cr0;
                o[ct][2] *= cr1; o[ct][3] *= cr1;
            }

            // ---- pack P into A-fragments (4 k-steps of 16 keys) ----
            uint32_t aP[4][4];
            #pragma unroll
            for (int j = 0; j < 4; j++) {
                aP[j][0] = bf16x2_pack(s[2 * j][0],     s[2 * j][1]);
                aP[j][1] = bf16x2_pack(s[2 * j][2],     s[2 * j][3]);
                aP[j][2] = bf16x2_pack(s[2 * j + 1][0], s[2 * j + 1][1]);
                aP[j][3] = bf16x2_pack(s[2 * j + 1][2], s[2 * j + 1][3]);
            }

            // ---- O += P * Vw ----
            const uint32_t v_b = sbase + OFF_V + buf * 16384 + sub * 8192;
            #pragma unroll
            for (int ct = 0; ct < 8; ct++) {
                const uint32_t roff = (ct * 8 + (lane & 7)) * 128 + (lane >> 3) * 16;
                uint32_t vb[8];
                LDMX4(vb,     v_b + SW128(roff));
                LDMX4(vb + 4, v_b + SW128(roff + 64));
                #pragma unroll
                for (int j = 0; j < 4; j++)
                    MMA16816(o[ct], aP[j], vb[2 * j], vb[2 * j + 1]);
            }
        }
        __syncthreads();
    }

    // ---- epilogue: stage O[c][q] in smem, coalesced add-residual write ----
    const float g0 = gamma[0];
    const float inv0 = g0 / den0, inv1 = g0 / den1;
    float* Ost = (float*)smem;    // [64 c][128 q]
    #pragma unroll
    for (int ct = 0; ct < 8; ct++) {
        const int c = ct * 8 + 2 * u;
        Ost[c * 128 + q0w + g]             = o[ct][0] * inv0;
        Ost[(c + 1) * 128 + q0w + g]       = o[ct][1] * inv0;
        Ost[c * 128 + q0w + g + 8]         = o[ct][2] * inv1;
        Ost[(c + 1) * 128 + q0w + g + 8]   = o[ct][3] * inv1;
    }
    __syncthreads();
    for (int e = tid; e < 2048; e += 256) {
        const int c = e >> 5, q4 = (e & 31) * 4;
        float4 ov = *(float4*)&Ost[c * 128 + q4];
        const size_t off = (size_t)(b * 64 + c) * HW + n0 + q4;
        const float4 xv = *(const float4*)&x[off];
        ov.x += xv.x; ov.y += xv.y; ov.z += xv.z; ov.w += xv.w;
        *(float4*)&out[off] = ov;
    }
}

// ================= launch =================
extern "C" void kernel_launch(void* const* d_in, const int* in_sizes, int n_in,
                              void* d_out, int out_size)
{
    (void)in_sizes; (void)n_in; (void)out_size;
    const float* x       = (const float*)d_in[0];
    const float* Wq      = (const float*)d_in[1];
    const float* bq      = (const float*)d_in[2];
    const float* Wk      = (const float*)d_in[3];
    const float* bk      = (const float*)d_in[4];
    const float* Wv      = (const float*)d_in[5];
    const float* bv      = (const float*)d_in[6];
    const float* We1     = (const float*)d_in[7];
    const float* be1     = (const float*)d_in[8];
    const float* bn_w    = (const float*)d_in[9];
    const float* bn_b    = (const float*)d_in[10];
    const float* bn_mean = (const float*)d_in[11];
    const float* bn_var  = (const float*)d_in[12];
    const float* We2     = (const float*)d_in[13];
    const float* be2     = (const float*)d_in[14];
    const float* gamma   = (const float*)d_in[15];
    const float* beta    = (const float*)d_in[16];
    float* out = (float*)d_out;

    edge_kernel<<<dim3(16, NB), 256>>>(x, We1, be1, bn_w, bn_b, bn_mean, bn_var,
                                       We2, be2, beta);
    qkv_kernel<<<dim3(64, NB), 256>>>(x, Wq, bq, Wk, bk, Wv, bv);

    cudaFuncSetAttribute(flash_kernel, cudaFuncAttributeMaxDynamicSharedMemorySize,
                         SMEM_BYTES);
    flash_kernel<<<dim3(32, NB), 256, SMEM_BYTES>>>(x, gamma, out);
}

// round 6
// speedup vs baseline: 1.9840x; 1.0820x over previous
#include <cuda_runtime.h>
#include <cuda_bf16.h>
#include <cstdint>

#define HW    4096
#define NB    4
#define LOG2E 1.44269504088896340736f

// ---------------- scratch (device globals: allocation-free) ----------------
__device__ __nv_bfloat16 g_Qh[NB * HW * 64];   // [b][n][c] hi, pre-scaled by log2e
__device__ __nv_bfloat16 g_Ql[NB * HW * 64];   // [b][n][c] lo
__device__ __nv_bfloat16 g_Kh[NB * HW * 64];   // [b][n][c] hi
__device__ __nv_bfloat16 g_Kl[NB * HW * 64];   // [b][n][c] lo
__device__ __nv_bfloat16 g_Vb[NB * 64 * HW];   // [b][c][m]  (w folded in), bf16
__device__ float         g_w [NB * HW];        // w[m] = 1 + beta*edge

// ---------------- f32x2 packed-FMA helpers ----------------
__device__ __forceinline__ double dup2(float x) {
    double r; asm("mov.b64 %0, {%1,%1};" : "=d"(r) : "f"(x)); return r;
}
__device__ __forceinline__ void ffma2(double &d, double a, double b) {
    asm("fma.rn.f32x2 %0, %1, %2, %0;" : "+d"(d) : "d"(a), "d"(b));
}
__device__ __forceinline__ void unpack2(double v, float &lo, float &hi) {
    asm("mov.b64 {%0,%1}, %2;" : "=f"(lo), "=f"(hi) : "d"(v));
}
__device__ __forceinline__ float ex2f(float x) {
    float r; asm("ex2.approx.f32 %0, %1;" : "=f"(r) : "f"(x)); return r;
}
__device__ __forceinline__ uint32_t bf16x2_pack(float lo, float hi) {
    uint32_t r; asm("cvt.rn.bf16x2.f32 %0, %1, %2;" : "=r"(r) : "f"(hi), "f"(lo));
    return r;
}
__device__ __forceinline__ uint32_t smem_u32(const void* p) {
    uint32_t a;
    asm("{ .reg .u64 t; cvta.to.shared.u64 t, %1; cvt.u32.u64 %0, t; }"
        : "=r"(a) : "l"(p));
    return a;
}

#define SW128(o) ((o) ^ (((o) >> 3) & 0x70))

// ---------------- mma.sync / ldmatrix ----------------
#define LDMX4(r, addr) \
    asm volatile("ldmatrix.sync.aligned.m8n8.x4.shared.b16 {%0,%1,%2,%3}, [%4];" \
        : "=r"((r)[0]), "=r"((r)[1]), "=r"((r)[2]), "=r"((r)[3]) : "r"(addr))

#define MMA16816(d, a, b0, b1) \
    asm volatile("mma.sync.aligned.m16n8k16.row.col.f32.bf16.bf16.f32 " \
        "{%0,%1,%2,%3},{%4,%5,%6,%7},{%8,%9},{%0,%1,%2,%3};" \
        : "+f"((d)[0]), "+f"((d)[1]), "+f"((d)[2]), "+f"((d)[3]) \
        : "r"((a)[0]), "r"((a)[1]), "r"((a)[2]), "r"((a)[3]), "r"(b0), "r"(b1))

// ================= kernel 1: edge detector -> g_w =================
// 128 CTAs; each CTA: 2 image rows (128 px), 256 thr = 2 thr/px (32 ch each).
// x halo tile staged in smem with padded columns (66-wide, zero borders).
#define XT_FLOATS (64 * 4 * 66)                 // 16896
#define WS_FLOATS (64 * 9 * 32)                 // 18432
#define RED_STRIDE 34
#define RED_FLOATS (128 * RED_STRIDE)           // 4352
#define EDGE_SMEM ((XT_FLOATS + WS_FLOATS + RED_FLOATS) * 4)   // 158720 B

__global__ __launch_bounds__(256) void edge_kernel(
    const float* __restrict__ x,  const float* __restrict__ We1,
    const float* __restrict__ be1,
    const float* __restrict__ bn_w, const float* __restrict__ bn_b,
    const float* __restrict__ bn_mean, const float* __restrict__ bn_var,
    const float* __restrict__ We2, const float* __restrict__ be2,
    const float* __restrict__ beta)
{
    extern __shared__ float es[];
    float* xt  = es;                         // [64ch][4r][66c]
    float* Wsh = es + XT_FLOATS;             // [(cc*9+k)*32 + ch]
    float* red = es + XT_FLOATS + WS_FLOATS; // [128px][34]
    __shared__ float s_sc[32], s_sh[32], s_w2[32];

    const int tid = threadIdx.x;
    const int b   = blockIdx.y;
    const int pr0 = blockIdx.x * 2;          // image row base (2 rows per CTA)

    if (tid < 32) {
        float s = bn_w[tid] * rsqrtf(bn_var[tid] + 1e-5f);
        s_sc[tid] = s;
        s_sh[tid] = (be1[tid] - bn_mean[tid]) * s + bn_b[tid];
        s_w2[tid] = We2[tid];
    }

    // weights transposed: Wsh[(cc*9+k)*32+ch] = We1[ch][cc][k]
    for (int e = tid; e < WS_FLOATS; e += 256) {
        int ch = e & 31, rest = e >> 5;
        int k = rest % 9, cc = rest / 9;
        Wsh[e] = We1[(ch * 64 + cc) * 9 + k];
    }
    // x halo tile with zero-padded borders
    for (int e = tid; e < XT_FLOATS; e += 256) {
        int c66 = e % 66, rest = e / 66;
        int r = rest & 3, ch = rest >> 2;
        int ir = pr0 - 1 + r, ic = c66 - 1;
        float v = 0.f;
        if (ir >= 0 && ir < 64 && ic >= 0 && ic < 64)
            v = x[(size_t)(b * 64 + ch) * HW + ir * 64 + ic];
        xt[e] = v;
    }
    __syncthreads();

    const int px  = tid & 127;
    const int cu  = tid >> 7;                // channel chunk (0/1)
    const int pr  = px >> 6, col = px & 63;

    double acc2[16];
    #pragma unroll
    for (int i = 0; i < 16; i++) acc2[i] = 0.0;

    for (int ccl = 0; ccl < 32; ccl++) {
        const int cc = cu * 32 + ccl;
        const float* xb = &xt[(cc * 4 + pr) * 66 + col];
        float xv[9];
        #pragma unroll
        for (int ry = 0; ry < 3; ry++)
            #pragma unroll
            for (int rx = 0; rx < 3; rx++)
                xv[ry * 3 + rx] = xb[ry * 66 + rx];
        #pragma unroll
        for (int k = 0; k < 9; k++) {
            double dv = dup2(xv[k]);
            const double* wrow = (const double*)&Wsh[(cc * 9 + k) * 32];
            #pragma unroll
            for (int c2 = 0; c2 < 16; c2++) ffma2(acc2[c2], dv, wrow[c2]);
        }
    }

    // combine the two channel chunks, then BN/ReLU/1x1/sigmoid
    if (cu == 1) {
        double* rp = (double*)&red[px * RED_STRIDE];
        #pragma unroll
        for (int i = 0; i < 16; i++) rp[i] = acc2[i];
    }
    __syncthreads();
    if (cu == 0) {
        const double* rp = (const double*)&red[px * RED_STRIDE];
        float e2 = be2[0];
        #pragma unroll
        for (int c2 = 0; c2 < 16; c2++) {
            float a0, a1, p0, p1;
            unpack2(acc2[c2], a0, a1);
            unpack2(rp[c2],   p0, p1);
            a0 += p0; a1 += p1;
            const int ch = c2 * 2;
            float r0 = fmaxf(a0 * s_sc[ch]     + s_sh[ch],     0.f);
            float r1 = fmaxf(a1 * s_sc[ch + 1] + s_sh[ch + 1], 0.f);
            e2 += s_w2[ch] * r0 + s_w2[ch + 1] * r1;
        }
        float sig = 1.f / (1.f + ex2f(-e2 * LOG2E));
        g_w[b * HW + pr0 * 64 + px] = 1.f + beta[0] * sig;
    }
}

// ================= kernel 2: QKV projections -> bf16 hi/lo =================
__global__ __launch_bounds__(256) void qkv_kernel(
    const float* __restrict__ x,
    const float* __restrict__ Wq, const float* __restrict__ bq,
    const float* __restrict__ Wk, const float* __restrict__ bk,
    const float* __restrict__ Wv, const float* __restrict__ bv)
{
    __shared__ __align__(16) float xs[64 * 64];
    __shared__ __align__(16) float WTq[32 * 64];
    __shared__ __align__(16) float WTk[32 * 64];
    __shared__ __align__(16) float WTv[32 * 64];

    const int tid = threadIdx.x;
    const int b   = blockIdx.y;
    const int n0  = blockIdx.x * 64;

    for (int e = tid; e < 4096; e += 256) {
        int c = e >> 6, j = e & 63;
        xs[c * 64 + j] = x[(size_t)(b * 64 + c) * HW + n0 + j];
    }

    const int tn = tid & 15, to = tid >> 4;
    double aq[4][2], ak[4][2], av[4][2];
    #pragma unroll
    for (int i = 0; i < 4; i++) {
        aq[i][0] = aq[i][1] = 0.0; ak[i][0] = ak[i][1] = 0.0; av[i][0] = av[i][1] = 0.0;
    }

    for (int chunk = 0; chunk < 2; chunk++) {
        __syncthreads();
        for (int e = tid; e < 2048; e += 256) {
            int o = e & 63, c = e >> 6;
            WTq[c * 64 + o] = Wq[o * 64 + chunk * 32 + c];
            WTk[c * 64 + o] = Wk[o * 64 + chunk * 32 + c];
            WTv[c * 64 + o] = Wv[o * 64 + chunk * 32 + c];
        }
        __syncthreads();
        #pragma unroll 4
        for (int cc = 0; cc < 32; cc++) {
            const float4 xv = *(const float4*)&xs[(chunk * 32 + cc) * 64 + tn * 4];
            const double2 wq = *(const double2*)&WTq[cc * 64 + to * 4];
            const double2 wk = *(const double2*)&WTk[cc * 64 + to * 4];
            const double2 wv = *(const double2*)&WTv[cc * 64 + to * 4];
            double dn[4] = {dup2(xv.x), dup2(xv.y), dup2(xv.z), dup2(xv.w)};
            #pragma unroll
            for (int jn = 0; jn < 4; jn++) {
                ffma2(aq[jn][0], dn[jn], wq.x); ffma2(aq[jn][1], dn[jn], wq.y);
                ffma2(ak[jn][0], dn[jn], wk.x); ffma2(ak[jn][1], dn[jn], wk.y);
                ffma2(av[jn][0], dn[jn], wv.x); ffma2(av[jn][1], dn[jn], wv.y);
            }
        }
    }

    const int ob = to * 4;
    float bqv[4], bkv[4], bvv[4];
    #pragma unroll
    for (int io = 0; io < 4; io++) {
        bqv[io] = bq[ob + io]; bkv[io] = bk[ob + io]; bvv[io] = bv[ob + io];
    }
    #pragma unroll
    for (int jn = 0; jn < 4; jn++) {
        const int n = n0 + tn * 4 + jn;
        float qf[4], kf[4], vf[4];
        unpack2(aq[jn][0], qf[0], qf[1]); unpack2(aq[jn][1], qf[2], qf[3]);
        unpack2(ak[jn][0], kf[0], kf[1]); unpack2(ak[jn][1], kf[2], kf[3]);
        unpack2(av[jn][0], vf[0], vf[1]); unpack2(av[jn][1], vf[2], vf[3]);
        const float wnj = g_w[b * HW + n];
        __nv_bfloat16 qh[4], ql[4], kh[4], kl[4];
        #pragma unroll
        for (int io = 0; io < 4; io++) {
            float q = (qf[io] + bqv[io]) * LOG2E;
            float k = kf[io] + bkv[io];
            qh[io] = __float2bfloat16(q);
            ql[io] = __float2bfloat16(q - __bfloat162float(qh[io]));
            kh[io] = __float2bfloat16(k);
            kl[io] = __float2bfloat16(k - __bfloat162float(kh[io]));
            g_Vb[((size_t)(b * 64 + ob + io)) * HW + n] =
                __float2bfloat16((vf[io] + bvv[io]) * wnj);
        }
        const size_t base = ((size_t)(b * HW + n)) * 64 + ob;
        *(__nv_bfloat162*)&g_Qh[base]     = __nv_bfloat162(qh[0], qh[1]);
        *(__nv_bfloat162*)&g_Qh[base + 2] = __nv_bfloat162(qh[2], qh[3]);
        *(__nv_bfloat162*)&g_Ql[base]     = __nv_bfloat162(ql[0], ql[1]);
        *(__nv_bfloat162*)&g_Ql[base + 2] = __nv_bfloat162(ql[2], ql[3]);
        *(__nv_bfloat162*)&g_Kh[base]     = __nv_bfloat162(kh[0], kh[1]);
        *(__nv_bfloat162*)&g_Kh[base + 2] = __nv_bfloat162(kh[2], kh[3]);
        *(__nv_bfloat162*)&g_Kl[base]     = __nv_bfloat162(kl[0], kl[1]);
        *(__nv_bfloat162*)&g_Kl[base + 2] = __nv_bfloat162(kl[2], kl[3]);
    }
}

// ================= kernel 3: mma.sync flash attention =================
#define OFF_QH 0            // 16KB  [128 tok][64c] bf16 SW128
#define OFF_QL 16384        // 16KB
#define OFF_K  32768        // 2 bufs * (KH 16KB + KL 16KB) = 64KB
#define OFF_V  98304        // 2 bufs * 16KB
#define OFF_AW 131072       // 2 bufs * 128 f32
#define SMEM_BYTES 132096

__global__ __launch_bounds__(256, 1) void flash_kernel(
    const float* __restrict__ x, const float* __restrict__ gamma,
    float* __restrict__ out)
{
    extern __shared__ char smem[];
    const uint32_t sbase = smem_u32(smem);
    const int tid  = threadIdx.x;
    const int lane = tid & 31, wid = tid >> 5;
    const int g    = lane >> 2;
    const int u    = lane & 3;
    const int q0w  = wid * 16;
    const int b    = blockIdx.y;
    const int n0   = blockIdx.x * 128;

    {
        const uint4* Qhg = (const uint4*)(g_Qh + ((size_t)(b * HW + n0)) * 64);
        const uint4* Qlg = (const uint4*)(g_Ql + ((size_t)(b * HW + n0)) * 64);
        for (int e = tid; e < 1024; e += 256) {
            int r = e >> 3, c8 = e & 7;
            uint32_t o = SW128(r * 128 + c8 * 16);
            *(uint4*)(smem + OFF_QH + o) = Qhg[e];
            *(uint4*)(smem + OFF_QL + o) = Qlg[e];
        }
        const uint4* KHg = (const uint4*)(g_Kh + ((size_t)(b * HW)) * 64);
        const uint4* KLg = (const uint4*)(g_Kl + ((size_t)(b * HW)) * 64);
        for (int e = tid; e < 1024; e += 256) {
            int r = e >> 3, c8 = e & 7;
            uint32_t o = SW128(r * 128 + c8 * 16);
            *(uint4*)(smem + OFF_K + o)         = KHg[e];
            *(uint4*)(smem + OFF_K + 16384 + o) = KLg[e];
        }
        const __nv_bfloat16* Vg = g_Vb + (size_t)b * 64 * HW;
        for (int e = tid; e < 1024; e += 256) {
            int c = e >> 4, j8 = e & 15;
            uint4 val = *(const uint4*)(Vg + (size_t)c * HW + j8 * 8);
            *(uint4*)(smem + OFF_V + (j8 >> 3) * 8192 +
                      SW128(c * 128 + (j8 & 7) * 16)) = val;
        }
        if (tid < 128) *(float*)(smem + OFF_AW + tid * 4) = fabsf(g_w[b * HW + tid]);
    }
    __syncthreads();

    uint32_t qh[4][4], ql[4][4];
    {
        const int row = q0w + (lane & 15);
        #pragma unroll
        for (int ks = 0; ks < 4; ks++) {
            const uint32_t cb = ks * 32 + (lane >> 4) * 16;
            LDMX4(qh[ks], sbase + OFF_QH + SW128(row * 128 + cb));
            LDMX4(ql[ks], sbase + OFF_QL + SW128(row * 128 + cb));
        }
    }

    float o[8][4];
    #pragma unroll
    for (int ct = 0; ct < 8; ct++)
        o[ct][0] = o[ct][1] = o[ct][2] = o[ct][3] = 0.f;
    float mrow0 = -1e30f, mrow1 = -1e30f, den0 = 0.f, den1 = 0.f;

    for (int t = 0; t < 32; t++) {
        const int buf = t & 1;

        if (t < 31) {
            const int m1 = (t + 1) * 128, nb = buf ^ 1;
            const uint4* KHg = (const uint4*)(g_Kh + ((size_t)(b * HW + m1)) * 64);
            const uint4* KLg = (const uint4*)(g_Kl + ((size_t)(b * HW + m1)) * 64);
            char* kb = smem + OFF_K + nb * 32768;
            for (int e = tid; e < 1024; e += 256) {
                int r = e >> 3, c8 = e & 7;
                uint32_t oo = SW128(r * 128 + c8 * 16);
                *(uint4*)(kb + oo)         = KHg[e];
                *(uint4*)(kb + 16384 + oo) = KLg[e];
            }
            const __nv_bfloat16* Vg = g_Vb + (size_t)b * 64 * HW + m1;
            char* vb = smem + OFF_V + nb * 16384;
            for (int e = tid; e < 1024; e += 256) {
                int c = e >> 4, j8 = e & 15;
                uint4 val = *(const uint4*)(Vg + (size_t)c * HW + j8 * 8);
                *(uint4*)(vb + (j8 >> 3) * 8192 +
                          SW128(c * 128 + (j8 & 7) * 16)) = val;
            }
            if (tid < 128)
                *(float*)(smem + OFF_AW + nb * 512 + tid * 4) =
                    fabsf(g_w[b * HW + m1 + tid]);
        }

        const uint32_t kh_b = sbase + OFF_K + buf * 32768;
        const uint32_t kl_b = kh_b + 16384;
        const float*   awp  = (const float*)(smem + OFF_AW + buf * 512);

        #pragma unroll
        for (int sub = 0; sub < 2; sub++) {
            float s[8][4];
            #pragma unroll
            for (int i = 0; i < 8; i++)
                s[i][0] = s[i][1] = s[i][2] = s[i][3] = 0.f;

            #pragma unroll
            for (int i = 0; i < 8; i++) {
                const int nt = sub * 8 + i;
                const uint32_t roff = (nt * 8 + (lane & 7)) * 128 + (lane >> 3) * 16;
                uint32_t bh[8], bl[8];
                LDMX4(bh,     kh_b + SW128(roff));
                LDMX4(bh + 4, kh_b + SW128(roff + 64));
                LDMX4(bl,     kl_b + SW128(roff));
                LDMX4(bl + 4, kl_b + SW128(roff + 64));
                #pragma unroll
                for (int ks = 0; ks < 4; ks++) {
                    MMA16816(s[i], qh[ks], bh[2 * ks], bh[2 * ks + 1]);
                    MMA16816(s[i], qh[ks], bl[2 * ks], bl[2 * ks + 1]);
                    MMA16816(s[i], ql[ks], bh[2 * ks], bh[2 * ks + 1]);
                }
            }

            float mx0 = s[0][0], mx1 = s[0][2];
            #pragma unroll
            for (int i = 0; i < 8; i++) {
                mx0 = fmaxf(mx0, fmaxf(s[i][0], s[i][1]));
                mx1 = fmaxf(mx1, fmaxf(s[i][2], s[i][3]));
            }
            mx0 = fmaxf(mx0, __shfl_xor_sync(0xffffffffu, mx0, 1));
            mx0 = fmaxf(mx0, __shfl_xor_sync(0xffffffffu, mx0, 2));
            mx1 = fmaxf(mx1, __shfl_xor_sync(0xffffffffu, mx1, 1));
            mx1 = fmaxf(mx1, __shfl_xor_sync(0xffffffffu, mx1, 2));

            const float mn0 = fmaxf(mrow0, mx0), mn1 = fmaxf(mrow1, mx1);
            const float cr0 = ex2f(mrow0 - mn0), cr1 = ex2f(mrow1 - mn1);
            mrow0 = mn0; mrow1 = mn1;

            float ws0 = 0.f, ws1 = 0.f;
            #pragma unroll
            for (int i = 0; i < 8; i++) {
                const float2 aw = *(const float2*)&awp[sub * 64 + i * 8 + 2 * u];
                s[i][0] = ex2f(s[i][0] - mn0);
                s[i][1] = ex2f(s[i][1] - mn0);
                s[i][2] = ex2f(s[i][2] - mn1);
                s[i][3] = ex2f(s[i][3] - mn1);
                ws0 += s[i][0] * aw.x + s[i][1] * aw.y;
                ws1 += s[i][2] * aw.x + s[i][3] * aw.y;
            }
            ws0 += __shfl_xor_sync(0xffffffffu, ws0, 1);
            ws0 += __shfl_xor_sync(0xffffffffu, ws0, 2);
            ws1 += __shfl_xor_sync(0xffffffffu, ws1, 1);
            ws1 += __shfl_xor_sync(0xffffffffu, ws1, 2);
            den0 = den0 * cr0 + ws0;
            den1 = den1 * cr1 + ws1;

            #pragma unroll
            for (int ct = 0; ct < 8; ct++) {
                o[ct][0] *= cr0; o[ct][1] *= cr0;
                o[ct][2] *= cr1; o[ct][3] *= cr1;
            }

            uint32_t aP[4][4];
            #pragma unroll
            for (int j = 0; j < 4; j++) {
                aP[j][0] = bf16x2_pack(s[2 * j][0],     s[2 * j][1]);
                aP[j][1] = bf16x2_pack(s[2 * j][2],     s[2 * j][3]);
                aP[j][2] = bf16x2_pack(s[2 * j + 1][0], s[2 * j + 1][1]);
                aP[j][3] = bf16x2_pack(s[2 * j + 1][2], s[2 * j + 1][3]);
            }

            const uint32_t v_b = sbase + OFF_V + buf * 16384 + sub * 8192;
            #pragma unroll
            for (int ct = 0; ct < 8; ct++) {
                const uint32_t roff = (ct * 8 + (lane & 7)) * 128 + (lane >> 3) * 16;
                uint32_t vb[8];
                LDMX4(vb,     v_b + SW128(roff));
                LDMX4(vb + 4, v_b + SW128(roff + 64));
                #pragma unroll
                for (int j = 0; j < 4; j++)
                    MMA16816(o[ct], aP[j], vb[2 * j], vb[2 * j + 1]);
            }
        }
        __syncthreads();
    }

    const float g0 = gamma[0];
    const float inv0 = g0 / den0, inv1 = g0 / den1;
    float* Ost = (float*)smem;    // [64 c][128 q]
    #pragma unroll
    for (int ct = 0; ct < 8; ct++) {
        const int c = ct * 8 + 2 * u;
        Ost[c * 128 + q0w + g]             = o[ct][0] * inv0;
        Ost[(c + 1) * 128 + q0w + g]       = o[ct][1] * inv0;
        Ost[c * 128 + q0w + g + 8]         = o[ct][2] * inv1;
        Ost[(c + 1) * 128 + q0w + g + 8]   = o[ct][3] * inv1;
    }
    __syncthreads();
    for (int e = tid; e < 2048; e += 256) {
        const int c = e >> 5, q4 = (e & 31) * 4;
        float4 ov = *(float4*)&Ost[c * 128 + q4];
        const size_t off = (size_t)(b * 64 + c) * HW + n0 + q4;
        const float4 xv = *(const float4*)&x[off];
        ov.x += xv.x; ov.y += xv.y; ov.z += xv.z; ov.w += xv.w;
        *(float4*)&out[off] = ov;
    }
}

// ================= launch =================
extern "C" void kernel_launch(void* const* d_in, const int* in_sizes, int n_in,
                              void* d_out, int out_size)
{
    (void)in_sizes; (void)n_in; (void)out_size;
    const float* x       = (const float*)d_in[0];
    const float* Wq      = (const float*)d_in[1];
    const float* bq      = (const float*)d_in[2];
    const float* Wk      = (const float*)d_in[3];
    const float* bk      = (const float*)d_in[4];
    const float* Wv      = (const float*)d_in[5];
    const float* bv      = (const float*)d_in[6];
    const float* We1     = (const float*)d_in[7];
    const float* be1     = (const float*)d_in[8];
    const float* bn_w    = (const float*)d_in[9];
    const float* bn_b    = (const float*)d_in[10];
    const float* bn_mean = (const float*)d_in[11];
    const float* bn_var  = (const float*)d_in[12];
    const float* We2     = (const float*)d_in[13];
    const float* be2     = (const float*)d_in[14];
    const float* gamma   = (const float*)d_in[15];
    const float* beta    = (const float*)d_in[16];
    float* out = (float*)d_out;

    cudaFuncSetAttribute(edge_kernel, cudaFuncAttributeMaxDynamicSharedMemorySize,
                         EDGE_SMEM);
    edge_kernel<<<dim3(32, NB), 256, EDGE_SMEM>>>(x, We1, be1, bn_w, bn_b,
                                                  bn_mean, bn_var, We2, be2, beta);
    qkv_kernel<<<dim3(64, NB), 256>>>(x, Wq, bq, Wk, bk, Wv, bv);

    cudaFuncSetAttribute(flash_kernel, cudaFuncAttributeMaxDynamicSharedMemorySize,
                         SMEM_BYTES);
    flash_kernel<<<dim3(32, NB), 256, SMEM_BYTES>>>(x, gamma, out);
}